// round 16
// baseline (speedup 1.0000x reference)
#include <cuda_runtime.h>

// Resample2d (FlowNet2 bilinear warp), fixed shape B=4, C=64, H=384, W=512.
//
// R15: R14's winning 2D-tile footprint compaction, extended vertically.
//   Block = 32x8 threads covering a 32x16 output tile; each thread handles
//   two vertically ADJACENT pixels (y, y+1). Per-warp gather instructions
//   keep the proven 32-consecutive-x single-row geometry; the pixel pair's
//   tap rows overlap (y0..y0+2 instead of 2x2 disjoint rows), shrinking the
//   block's per-channel gather footprint another ~1.6x -> more L1D hits,
//   less miss-path work (the mechanism that made R14 win).

static constexpr int B = 4;
static constexpr int C = 64;
static constexpr int H = 384;
static constexpr int W = 512;
static constexpr int HW = H * W;

__global__ __launch_bounds__(256) void resample2d_kernel(
    const float* __restrict__ in1,
    const float* __restrict__ flow,
    float* __restrict__ out)
{
    int x  = blockIdx.x * 32 + (threadIdx.x & 31);
    int ty = threadIdx.x >> 5;                    // 0..7
    int y  = blockIdx.y * 16 + ty * 2;            // even row of the pair
    int b  = blockIdx.z;

    const float* fptr = flow + (size_t)b * 2 * HW;

    int   offA[4], offB[4];
    float wA[4],  wB[4];
    int pixA = y * W + x;
    int pixB = pixA + W;

    #pragma unroll
    for (int p = 0; p < 2; ++p) {
        int yy  = y + p;
        int pix = p ? pixB : pixA;
        float dx = fptr[pix];
        float dy = fptr[HW + pix];

        float xf = (float)x + dx;
        float yf = (float)yy + dy;
        float x0f = floorf(xf);
        float y0f = floorf(yf);
        float a  = xf - x0f;
        float bw = yf - y0f;

        int x0i = (int)x0f;
        int y0i = (int)y0f;
        int x0 = min(max(x0i,     0), W - 1);
        int x1 = min(max(x0i + 1, 0), W - 1);
        int y0 = min(max(y0i,     0), H - 1);
        int y1 = min(max(y0i + 1, 0), H - 1);

        int*   off = p ? offB : offA;
        float* wgt = p ? wB   : wA;
        off[0] = y0 * W + x0;
        off[1] = y0 * W + x1;
        off[2] = y1 * W + x0;
        off[3] = y1 * W + x1;
        wgt[0] = (1.0f - a) * (1.0f - bw);
        wgt[1] = a * (1.0f - bw);
        wgt[2] = (1.0f - a) * bw;
        wgt[3] = a * bw;
    }

    const float* src = in1 + (size_t)b * C * HW;
    float*       dst = out + (size_t)b * C * HW;

    #pragma unroll 2
    for (int c = 0; c < C; ++c) {
        float a0 = __ldg(src + offA[0]);
        float a1 = __ldg(src + offA[1]);
        float a2 = __ldg(src + offA[2]);
        float a3 = __ldg(src + offA[3]);
        float b0 = __ldg(src + offB[0]);
        float b1 = __ldg(src + offB[1]);
        float b2 = __ldg(src + offB[2]);
        float b3 = __ldg(src + offB[3]);

        dst[pixA] = wA[0] * a0 + wA[1] * a1 + wA[2] * a2 + wA[3] * a3;
        dst[pixB] = wB[0] * b0 + wB[1] * b1 + wB[2] * b2 + wB[3] * b3;

        src += HW;
        dst += HW;
    }
}

extern "C" void kernel_launch(void* const* d_in, const int* in_sizes, int n_in,
                              void* d_out, int out_size)
{
    const float* in1  = (const float*)d_in[0];
    const float* flow = (const float*)d_in[1];
    float*       out  = (float*)d_out;

    dim3 grid(W / 32, H / 16, B);   // 16 x 24 x 4 = 1536 blocks
    resample2d_kernel<<<grid, 256>>>(in1, flow, out);
}

// round 17
// speedup vs baseline: 1.0958x; 1.0958x over previous
#include <cuda_runtime.h>

// Resample2d (FlowNet2 bilinear warp), fixed shape B=4, C=64, H=384, W=512.
//
// R16: R14's exact per-thread code (1 px/thread, 32 regs — every
// multi-px/thread variant lost on occupancy), with the block grown to
// 512 threads = 32x16 output tile. 16 co-resident warps share overlapping
// tap rows (y-1..y+17), cutting per-output L2 gather traffic ~15% vs R14's
// 32x8 tile and densifying L1D reuse — the footprint-compaction mechanism
// that produced the R14 win, applied one step further.

static constexpr int B = 4;
static constexpr int C = 64;
static constexpr int H = 384;
static constexpr int W = 512;
static constexpr int HW = H * W;

__global__ __launch_bounds__(512) void resample2d_kernel(
    const float* __restrict__ in1,
    const float* __restrict__ flow,
    float* __restrict__ out)
{
    int x = blockIdx.x * 32 + (threadIdx.x & 31);
    int y = blockIdx.y * 16 + (threadIdx.x >> 5);
    int b = blockIdx.z;

    int pix = y * W + x;
    const float* fptr = flow + (size_t)b * 2 * HW;
    float dx = fptr[pix];
    float dy = fptr[HW + pix];

    float xf = (float)x + dx;
    float yf = (float)y + dy;
    float x0f = floorf(xf);
    float y0f = floorf(yf);
    float a  = xf - x0f;            // frac x
    float bw = yf - y0f;            // frac y

    int x0i = (int)x0f;
    int y0i = (int)y0f;
    int x0 = min(max(x0i,     0), W - 1);
    int x1 = min(max(x0i + 1, 0), W - 1);
    int y0 = min(max(y0i,     0), H - 1);
    int y1 = min(max(y0i + 1, 0), H - 1);

    float w00 = (1.0f - a) * (1.0f - bw);
    float w10 = a * (1.0f - bw);
    float w01 = (1.0f - a) * bw;
    float w11 = a * bw;

    int i00 = y0 * W + x0;
    int i10 = y0 * W + x1;
    int i01 = y1 * W + x0;
    int i11 = y1 * W + x1;

    const float* p = in1 + (size_t)b * C * HW;
    float*       o = out + (size_t)b * C * HW + pix;

    #pragma unroll 4
    for (int c = 0; c < C; ++c) {
        size_t off = (size_t)c * HW;
        float v00 = __ldg(p + off + i00);
        float v10 = __ldg(p + off + i10);
        float v01 = __ldg(p + off + i01);
        float v11 = __ldg(p + off + i11);
        o[off] = w00 * v00 + w10 * v10 + w01 * v01 + w11 * v11;
    }
}

extern "C" void kernel_launch(void* const* d_in, const int* in_sizes, int n_in,
                              void* d_out, int out_size)
{
    const float* in1  = (const float*)d_in[0];
    const float* flow = (const float*)d_in[1];
    float*       out  = (float*)d_out;

    dim3 grid(W / 32, H / 16, B);   // 16 x 24 x 4 = 1536 blocks
    resample2d_kernel<<<grid, 512>>>(in1, flow, out);
}